// round 1
// baseline (speedup 1.0000x reference)
#include <cuda_runtime.h>
#include <cstdint>

// FWHT over contiguous groups of 128 fp32 elements.
// One warp per group; each thread owns 4 contiguous elements (float4).
// Stages: h=1,2 intra-thread; h=4,8,16,32,64 via shfl.xor lane deltas 1,2,4,8,16.

__global__ void __launch_bounds__(256) fwht128_kernel(
    const float4* __restrict__ in, float4* __restrict__ out, unsigned int n4)
{
    unsigned int idx = blockIdx.x * blockDim.x + threadIdx.x;
    if (idx >= n4) return;

    float4 v = in[idx];

    // stage h=1 (within float4: pairs (x,y),(z,w))
    float a0 = v.x + v.y;
    float a1 = v.x - v.y;
    float a2 = v.z + v.w;
    float a3 = v.z - v.w;

    // stage h=2 (within float4: pairs (0,2),(1,3))
    float b0 = a0 + a2;
    float b1 = a1 + a3;
    float b2 = a0 - a2;
    float b3 = a1 - a3;

    // stages h=4..64 -> cross-thread butterflies within the warp
    unsigned int lane = threadIdx.x & 31u;
    #pragma unroll
    for (int d = 1; d <= 16; d <<= 1) {
        float p0 = __shfl_xor_sync(0xffffffffu, b0, d);
        float p1 = __shfl_xor_sync(0xffffffffu, b1, d);
        float p2 = __shfl_xor_sync(0xffffffffu, b2, d);
        float p3 = __shfl_xor_sync(0xffffffffu, b3, d);
        if (lane & (unsigned)d) {
            b0 = p0 - b0;
            b1 = p1 - b1;
            b2 = p2 - b2;
            b3 = p3 - b3;
        } else {
            b0 = b0 + p0;
            b1 = b1 + p1;
            b2 = b2 + p2;
            b3 = b3 + p3;
        }
    }

    const float SCALE = 0.08838834764831845f;  // 1/sqrt(128)
    float4 r;
    r.x = b0 * SCALE;
    r.y = b1 * SCALE;
    r.z = b2 * SCALE;
    r.w = b3 * SCALE;
    out[idx] = r;
}

extern "C" void kernel_launch(void* const* d_in, const int* in_sizes, int n_in,
                              void* d_out, int out_size)
{
    const float4* x = (const float4*)d_in[0];
    float4* y = (float4*)d_out;
    unsigned int n4 = (unsigned int)(in_sizes[0] / 4);  // 67108864/4 = 16777216

    const int BLOCK = 256;
    unsigned int grid = (n4 + BLOCK - 1) / BLOCK;
    fwht128_kernel<<<grid, BLOCK>>>(x, y, n4);
}

// round 2
// speedup vs baseline: 1.0590x; 1.0590x over previous
#include <cuda_runtime.h>
#include <cstdint>

// FWHT over contiguous groups of 128 fp32 elements.
// One warp per group; each thread owns 4 contiguous elements (float4).
// Stages: h=1,2 intra-thread; h=4..64 via shfl.xor lane deltas 1,2,4,8,16.
// Unroll U=4: front-batched LDG.128 x4 (MLP=4) + 4 interleaved shuffle chains.

#define U 4

__global__ void __launch_bounds__(256) fwht128_kernel(
    const float4* __restrict__ in, float4* __restrict__ out)
{
    unsigned int base = blockIdx.x * (256u * U) + threadIdx.x;
    unsigned int lane = threadIdx.x & 31u;

    // Front-batched loads: 4 independent LDG.128 in flight per thread.
    float4 v[U];
    #pragma unroll
    for (int u = 0; u < U; ++u)
        v[u] = __ldcs(in + base + u * 256u);

    // Intra-thread stages h=1, h=2.
    float b[U][4];
    #pragma unroll
    for (int u = 0; u < U; ++u) {
        float a0 = v[u].x + v[u].y;
        float a1 = v[u].x - v[u].y;
        float a2 = v[u].z + v[u].w;
        float a3 = v[u].z - v[u].w;
        b[u][0] = a0 + a2;
        b[u][1] = a1 + a3;
        b[u][2] = a0 - a2;
        b[u][3] = a1 - a3;
    }

    // Cross-lane stages h=4,8,16,32,64: 4 independent chains interleaved.
    #pragma unroll
    for (int d = 1; d <= 16; d <<= 1) {
        bool hi = (lane & (unsigned)d) != 0u;
        #pragma unroll
        for (int u = 0; u < U; ++u) {
            #pragma unroll
            for (int k = 0; k < 4; ++k) {
                float p = __shfl_xor_sync(0xffffffffu, b[u][k], d);
                b[u][k] = hi ? (p - b[u][k]) : (b[u][k] + p);
            }
        }
    }

    const float S = 0.08838834764831845f;  // 1/sqrt(128)
    #pragma unroll
    for (int u = 0; u < U; ++u) {
        float4 r;
        r.x = b[u][0] * S;
        r.y = b[u][1] * S;
        r.z = b[u][2] * S;
        r.w = b[u][3] * S;
        __stcs(out + base + u * 256u, r);
    }
}

extern "C" void kernel_launch(void* const* d_in, const int* in_sizes, int n_in,
                              void* d_out, int out_size)
{
    const float4* x = (const float4*)d_in[0];
    float4* y = (float4*)d_out;
    // 4*4096*4096 = 67108864 floats = 16777216 float4s; 16384 blocks * 256 thr * 4 = exact.
    unsigned int n4 = (unsigned int)(in_sizes[0] / 4);
    unsigned int grid = n4 / (256u * U);
    fwht128_kernel<<<grid, 256>>>(x, y);
}